// round 1
// baseline (speedup 1.0000x reference)
#include <cuda_runtime.h>
#include <cuda_bf16.h>
#include <math.h>

#define B 4
#define S 2048
#define E 1024
#define H 16
#define HD 64
#define EPS 1.1920928955078125e-07f

#define BM 64
#define BN 64
#define PAD 68
#define SMEM_ATTN (4 * 64 * PAD * 4)

// Scratch (allocation-free rule: __device__ globals)
__device__ float g_Qn[B * H * S * HD];   // 32 MB, [bh][s][d]
__device__ float g_Kn[B * H * S * HD];   // 32 MB
__device__ float g_ctx[B * S * E];       // 32 MB, [b*s][e]

#define C4(v, i) (reinterpret_cast<const float*>(&(v))[i])

// ---------------------------------------------------------------------------
// Kernel 1: fused RMSNorm + RoPE for Q and K, transpose to [B,H,S,HD]
// One warp per (b,s,h) row; lane j owns the RoPE pair (2j, 2j+1).
// ---------------------------------------------------------------------------
__global__ __launch_bounds__(256) void prep_kernel(
    const float* __restrict__ q, const float* __restrict__ k,
    const float* __restrict__ qw, const float* __restrict__ kw)
{
    int warp = (blockIdx.x * blockDim.x + threadIdx.x) >> 5;
    int lane = threadIdx.x & 31;
    // warp = (b*S + s)*H + h
    int h  = warp & (H - 1);
    int bs = warp >> 4;            // b*S + s
    int s  = bs & (S - 1);
    int b  = bs >> 11;             // /2048

    int gi = bs * E + h * HD + 2 * lane;
    float2 qv = *reinterpret_cast<const float2*>(q + gi);
    float2 kv = *reinterpret_cast<const float2*>(k + gi);

    // RoPE coefficients: inv_freq = 10000^(-lane/32), computed in double then
    // rounded to f32; angle multiplied in f32 to mirror the reference.
    double invd = exp2(-(double)lane * 0.4152410118609203); // log2(10000)/32
    float inv_f = (float)invd;
    float ang = (float)s * inv_f;
    float cs = cosf(ang), sn = sinf(ang);

    float w1q = qw[2 * lane], w2q = qw[2 * lane + 1];
    float w1k = kw[2 * lane], w2k = kw[2 * lane + 1];

    // rmsnorm(q)
    float ssq = qv.x * qv.x + qv.y * qv.y;
    float ssk = kv.x * kv.x + kv.y * kv.y;
    #pragma unroll
    for (int off = 16; off; off >>= 1) {
        ssq += __shfl_xor_sync(0xffffffff, ssq, off);
        ssk += __shfl_xor_sync(0xffffffff, ssk, off);
    }
    float rq = rsqrtf(ssq * (1.0f / HD) + EPS);
    float rk = rsqrtf(ssk * (1.0f / HD) + EPS);

    float qx1 = qv.x * rq * w1q, qx2 = qv.y * rq * w2q;
    float kx1 = kv.x * rk * w1k, kx2 = kv.y * rk * w2k;

    float2 qo = make_float2(qx1 * cs - qx2 * sn, qx1 * sn + qx2 * cs);
    float2 ko = make_float2(kx1 * cs - kx2 * sn, kx1 * sn + kx2 * cs);

    int oi = ((b * H + h) * S + s) * HD + 2 * lane;
    *reinterpret_cast<float2*>(g_Qn + oi) = qo;
    *reinterpret_cast<float2*>(g_Kn + oi) = ko;
}

// ---------------------------------------------------------------------------
// Kernel 2: flash attention, fp32. Block = (q-tile of 64 rows, one bh).
// 256 threads as 16x16; each thread owns a 4x4 micro-tile.
// Softmax kept in log2 domain (scale folds in log2(e); exp2f = 1 MUFU op).
// ---------------------------------------------------------------------------
__global__ __launch_bounds__(256) void attn_kernel(const float* __restrict__ v)
{
    extern __shared__ float sm[];
    float* sQ  = sm;                 // [64][PAD] row-major (r, d)
    float* sKt = sm + 64 * PAD;      // [64][PAD] (d, c)  transposed K
    float* sV  = sm + 2 * 64 * PAD;  // [64][PAD] (kpos, d)
    float* sP  = sm + 3 * 64 * PAD;  // [64][PAD] (r, c)

    int bh = blockIdx.y;
    int qt = blockIdx.x;
    int tid = threadIdx.x;
    int tx = tid & 15, ty = tid >> 4;

    const float* Qb = g_Qn + bh * (S * HD) + qt * BM * HD;
    const float* Kb = g_Kn + bh * (S * HD);
    int b = bh >> 4, h = bh & 15;
    const float* Vb = v + (b * S) * E + h * HD;   // stride E between kpos

    // scale = HD^-0.5 * log2(e), folded into Q once
    const float scale = 0.125f * 1.4426950408889634f;
    for (int i = tid; i < 64 * 16; i += 256) {
        int r = i >> 4, c4 = (i & 15) << 2;
        float4 f = *reinterpret_cast<const float4*>(Qb + r * HD + c4);
        f.x *= scale; f.y *= scale; f.z *= scale; f.w *= scale;
        *reinterpret_cast<float4*>(sQ + r * PAD + c4) = f;
    }

    float m[4], l[4], o[4][4];
    #pragma unroll
    for (int i = 0; i < 4; i++) {
        m[i] = -1e30f; l[i] = 0.f;
        #pragma unroll
        for (int j = 0; j < 4; j++) o[i][j] = 0.f;
    }

    for (int kt = 0; kt < S / BN; kt++) {
        __syncthreads();
        // load K (transposed into sKt) and V tile
        for (int i = tid; i < 64 * 16; i += 256) {
            int c = i >> 4, d4 = (i & 15) << 2;
            float4 kf = *reinterpret_cast<const float4*>(Kb + (kt * BN + c) * HD + d4);
            sKt[(d4 + 0) * PAD + c] = kf.x;
            sKt[(d4 + 1) * PAD + c] = kf.y;
            sKt[(d4 + 2) * PAD + c] = kf.z;
            sKt[(d4 + 3) * PAD + c] = kf.w;
            float4 vf = *reinterpret_cast<const float4*>(Vb + (kt * BN + c) * E + d4);
            *reinterpret_cast<float4*>(sV + c * PAD + d4) = vf;
        }
        __syncthreads();

        // scores: acc[i][j] = sum_d Q[r0+i][d] * K[c0+j][d]
        float acc[4][4];
        #pragma unroll
        for (int i = 0; i < 4; i++)
            #pragma unroll
            for (int j = 0; j < 4; j++) acc[i][j] = 0.f;

        #pragma unroll 4
        for (int kk = 0; kk < 64; kk += 4) {
            float4 qf[4], kf[4];
            #pragma unroll
            for (int i = 0; i < 4; i++)
                qf[i] = *reinterpret_cast<const float4*>(sQ + (ty * 4 + i) * PAD + kk);
            #pragma unroll
            for (int d = 0; d < 4; d++)
                kf[d] = *reinterpret_cast<const float4*>(sKt + (kk + d) * PAD + tx * 4);
            #pragma unroll
            for (int d = 0; d < 4; d++) {
                float kx = C4(kf[d], 0), ky = C4(kf[d], 1);
                float kz = C4(kf[d], 2), kw = C4(kf[d], 3);
                #pragma unroll
                for (int i = 0; i < 4; i++) {
                    float qd = C4(qf[i], d);
                    acc[i][0] = fmaf(qd, kx, acc[i][0]);
                    acc[i][1] = fmaf(qd, ky, acc[i][1]);
                    acc[i][2] = fmaf(qd, kz, acc[i][2]);
                    acc[i][3] = fmaf(qd, kw, acc[i][3]);
                }
            }
        }

        // online softmax (log2 domain) + write P to smem
        #pragma unroll
        for (int i = 0; i < 4; i++) {
            float mx = fmaxf(fmaxf(acc[i][0], acc[i][1]), fmaxf(acc[i][2], acc[i][3]));
            #pragma unroll
            for (int off = 8; off; off >>= 1)
                mx = fmaxf(mx, __shfl_xor_sync(0xffffffff, mx, off));
            float mn = fmaxf(m[i], mx);
            float al = exp2f(m[i] - mn);
            m[i] = mn;
            float rs = 0.f;
            #pragma unroll
            for (int j = 0; j < 4; j++) {
                float p = exp2f(acc[i][j] - mn);
                acc[i][j] = p;
                rs += p;
            }
            #pragma unroll
            for (int off = 8; off; off >>= 1)
                rs += __shfl_xor_sync(0xffffffff, rs, off);
            l[i] = l[i] * al + rs;
            #pragma unroll
            for (int j = 0; j < 4; j++) o[i][j] *= al;
            float4 pv = make_float4(acc[i][0], acc[i][1], acc[i][2], acc[i][3]);
            *reinterpret_cast<float4*>(sP + (ty * 4 + i) * PAD + tx * 4) = pv;
        }
        __syncthreads();

        // O += P * V : o[i][j] += sum_kpos P[r0+i][kpos] * V[kpos][d0+j]
        #pragma unroll 4
        for (int kk = 0; kk < 64; kk += 4) {
            float4 pf[4], vf[4];
            #pragma unroll
            for (int i = 0; i < 4; i++)
                pf[i] = *reinterpret_cast<const float4*>(sP + (ty * 4 + i) * PAD + kk);
            #pragma unroll
            for (int d = 0; d < 4; d++)
                vf[d] = *reinterpret_cast<const float4*>(sV + (kk + d) * PAD + tx * 4);
            #pragma unroll
            for (int d = 0; d < 4; d++) {
                float vx = C4(vf[d], 0), vy = C4(vf[d], 1);
                float vz = C4(vf[d], 2), vw = C4(vf[d], 3);
                #pragma unroll
                for (int i = 0; i < 4; i++) {
                    float pd = C4(pf[i], d);
                    o[i][0] = fmaf(pd, vx, o[i][0]);
                    o[i][1] = fmaf(pd, vy, o[i][1]);
                    o[i][2] = fmaf(pd, vz, o[i][2]);
                    o[i][3] = fmaf(pd, vw, o[i][3]);
                }
            }
        }
    }

    // epilogue: normalize and write ctx[b][row][h*HD + d]
    #pragma unroll
    for (int i = 0; i < 4; i++) {
        float inv = 1.0f / l[i];
        int grow = qt * BM + ty * 4 + i;
        float4 r = make_float4(o[i][0] * inv, o[i][1] * inv, o[i][2] * inv, o[i][3] * inv);
        *reinterpret_cast<float4*>(g_ctx + (b * S + grow) * E + h * HD + tx * 4) = r;
    }
}

// ---------------------------------------------------------------------------
// Kernel 3: out[m][j] = sum_k ctx[m][k] * W[j][k] + bias[j]
// BM=BN=64, BK=16, 256 threads, 4x4 micro-tiles.
// ---------------------------------------------------------------------------
__global__ __launch_bounds__(256) void proj_kernel(
    const float* __restrict__ W, const float* __restrict__ bias,
    float* __restrict__ out)
{
    __shared__ float sA[64 * 16];    // (m, k)
    __shared__ float sBt[16 * 68];   // (k, j)

    int tid = threadIdx.x;
    int tx = tid & 15, ty = tid >> 4;
    int jb = blockIdx.x * 64, mb = blockIdx.y * 64;
    int r = tid >> 2, c4 = (tid & 3) << 2;

    float acc[4][4];
    #pragma unroll
    for (int i = 0; i < 4; i++)
        #pragma unroll
        for (int j = 0; j < 4; j++) acc[i][j] = 0.f;

    for (int kt = 0; kt < E; kt += 16) {
        __syncthreads();
        float4 a = *reinterpret_cast<const float4*>(g_ctx + (mb + r) * E + kt + c4);
        *reinterpret_cast<float4*>(sA + r * 16 + c4) = a;
        float4 w = *reinterpret_cast<const float4*>(W + (jb + r) * E + kt + c4);
        sBt[(c4 + 0) * 68 + r] = w.x;
        sBt[(c4 + 1) * 68 + r] = w.y;
        sBt[(c4 + 2) * 68 + r] = w.z;
        sBt[(c4 + 3) * 68 + r] = w.w;
        __syncthreads();

        #pragma unroll
        for (int kk = 0; kk < 16; kk += 4) {
            float4 af[4], bf[4];
            #pragma unroll
            for (int i = 0; i < 4; i++)
                af[i] = *reinterpret_cast<const float4*>(sA + (ty * 4 + i) * 16 + kk);
            #pragma unroll
            for (int d = 0; d < 4; d++)
                bf[d] = *reinterpret_cast<const float4*>(sBt + (kk + d) * 68 + tx * 4);
            #pragma unroll
            for (int d = 0; d < 4; d++) {
                float bx = C4(bf[d], 0), by = C4(bf[d], 1);
                float bz = C4(bf[d], 2), bw = C4(bf[d], 3);
                #pragma unroll
                for (int i = 0; i < 4; i++) {
                    float ad = C4(af[i], d);
                    acc[i][0] = fmaf(ad, bx, acc[i][0]);
                    acc[i][1] = fmaf(ad, by, acc[i][1]);
                    acc[i][2] = fmaf(ad, bz, acc[i][2]);
                    acc[i][3] = fmaf(ad, bw, acc[i][3]);
                }
            }
        }
    }

    float4 bb = *reinterpret_cast<const float4*>(bias + jb + tx * 4);
    #pragma unroll
    for (int i = 0; i < 4; i++) {
        float4 rv = make_float4(acc[i][0] + bb.x, acc[i][1] + bb.y,
                                acc[i][2] + bb.z, acc[i][3] + bb.w);
        *reinterpret_cast<float4*>(out + (mb + ty * 4 + i) * E + jb + tx * 4) = rv;
    }
}

// ---------------------------------------------------------------------------
extern "C" void kernel_launch(void* const* d_in, const int* in_sizes, int n_in,
                              void* d_out, int out_size)
{
    const float* q    = (const float*)d_in[0];
    const float* k    = (const float*)d_in[1];
    const float* v    = (const float*)d_in[2];
    const float* qw   = (const float*)d_in[3];
    const float* kw   = (const float*)d_in[4];
    const float* W    = (const float*)d_in[5];
    const float* bias = (const float*)d_in[6];
    float* out = (float*)d_out;

    cudaFuncSetAttribute(attn_kernel, cudaFuncAttributeMaxDynamicSharedMemorySize,
                         SMEM_ATTN);

    // 1) norm + rope: one warp per (b,s,h) row
    prep_kernel<<<(B * S * H) / 8, 256>>>(q, k, qw, kw);

    // 2) flash attention: grid = (q-tiles, b*h)
    attn_kernel<<<dim3(S / BM, B * H), 256, SMEM_ATTN>>>(v);

    // 3) output projection
    proj_kernel<<<dim3(E / 64, (B * S) / 64), 256>>>(W, bias, out);
}

// round 6
// speedup vs baseline: 1.6937x; 1.6937x over previous
#include <cuda_runtime.h>
#include <cuda_bf16.h>
#include <math.h>
#include <stdint.h>

#define B 4
#define S 2048
#define E 1024
#define H 16
#define HD 64
#define EPS 1.1920928955078125e-07f

#define BMA 128      // q rows per CTA (attn)
#define BNA 64       // kv cols per tile
#define LDT 72       // smem row stride (bf16 elems) = 144B
#define SMEM_ATTN 73728

// ---------------- scratch (__device__ globals; no allocs allowed) -----------
__device__ float g_Qn[B*H*S*HD];   // fp32 head-major (R1-proven prep output)
__device__ float g_Kn[B*H*S*HD];
__device__ __nv_bfloat16 g_Qh[B*H*S*HD], g_Ql[B*H*S*HD];
__device__ __nv_bfloat16 g_Kh[B*H*S*HD], g_Kl[B*H*S*HD];
__device__ __nv_bfloat16 g_Vh[B*H*S*HD], g_Vl[B*H*S*HD];
__device__ float g_ctx[B*S*E];

#define C4(v, i) (reinterpret_cast<const float*>(&(v))[i])

// ---------------- helpers ---------------------------------------------------
__device__ __forceinline__ void mma16816(float d[4], const uint32_t a[4], const uint32_t b[2]) {
    asm volatile(
        "mma.sync.aligned.m16n8k16.row.col.f32.bf16.bf16.f32 "
        "{%0,%1,%2,%3},{%4,%5,%6,%7},{%8,%9},{%0,%1,%2,%3};"
        : "+f"(d[0]), "+f"(d[1]), "+f"(d[2]), "+f"(d[3])
        : "r"(a[0]), "r"(a[1]), "r"(a[2]), "r"(a[3]), "r"(b[0]), "r"(b[1]));
}
__device__ __forceinline__ uint32_t packb(__nv_bfloat16 x, __nv_bfloat16 y) {
    __nv_bfloat162 t = __halves2bfloat162(x, y);
    return *reinterpret_cast<uint32_t*>(&t);
}
__device__ __forceinline__ uint32_t lds32(const __nv_bfloat16* p) {
    return *reinterpret_cast<const uint32_t*>(p);
}

// ---------------- kernel 1: rmsnorm + rope (EXACT copy of R1-passing) -------
__global__ __launch_bounds__(256) void prep_kernel(
    const float* __restrict__ q, const float* __restrict__ k,
    const float* __restrict__ qw, const float* __restrict__ kw)
{
    int warp = (blockIdx.x * blockDim.x + threadIdx.x) >> 5;
    int lane = threadIdx.x & 31;
    int h  = warp & (H - 1);
    int bs = warp >> 4;            // b*S + s
    int s  = bs & (S - 1);
    int b  = bs >> 11;             // /2048

    int gi = bs * E + h * HD + 2 * lane;
    float2 qv = *reinterpret_cast<const float2*>(q + gi);
    float2 kv = *reinterpret_cast<const float2*>(k + gi);

    double invd = exp2(-(double)lane * 0.4152410118609203); // log2(10000)/32
    float inv_f = (float)invd;
    float ang = (float)s * inv_f;
    float cs = cosf(ang), sn = sinf(ang);

    float w1q = qw[2 * lane], w2q = qw[2 * lane + 1];
    float w1k = kw[2 * lane], w2k = kw[2 * lane + 1];

    float ssq = qv.x * qv.x + qv.y * qv.y;
    float ssk = kv.x * kv.x + kv.y * kv.y;
    #pragma unroll
    for (int off = 16; off; off >>= 1) {
        ssq += __shfl_xor_sync(0xffffffff, ssq, off);
        ssk += __shfl_xor_sync(0xffffffff, ssk, off);
    }
    float rq = rsqrtf(ssq * (1.0f / HD) + EPS);
    float rk = rsqrtf(ssk * (1.0f / HD) + EPS);

    float qx1 = qv.x * rq * w1q, qx2 = qv.y * rq * w2q;
    float kx1 = kv.x * rk * w1k, kx2 = kv.y * rk * w2k;

    float2 qo = make_float2(qx1 * cs - qx2 * sn, qx1 * sn + qx2 * cs);
    float2 ko = make_float2(kx1 * cs - kx2 * sn, kx1 * sn + kx2 * cs);

    int oi = ((b * H + h) * S + s) * HD + 2 * lane;
    *reinterpret_cast<float2*>(g_Qn + oi) = qo;
    *reinterpret_cast<float2*>(g_Kn + oi) = ko;
}

// ---------------- kernel 2a: fp32 Q/K -> bf16 hi/lo (scale folded in Q) -----
__global__ __launch_bounds__(256) void convqk_kernel()
{
    int u = blockIdx.x * 256 + threadIdx.x;   // pair id
    int i = u * 2;
    const float sc = 0.125f * 1.4426950408889634f; // HD^-0.5 * log2(e)
    float2 qv = *reinterpret_cast<const float2*>(g_Qn + i);
    float2 kv = *reinterpret_cast<const float2*>(g_Kn + i);
    qv.x *= sc; qv.y *= sc;

    __nv_bfloat16 q0 = __float2bfloat16_rn(qv.x), q1 = __float2bfloat16_rn(qv.y);
    __nv_bfloat16 k0 = __float2bfloat16_rn(kv.x), k1 = __float2bfloat16_rn(kv.y);
    reinterpret_cast<uint32_t*>(g_Qh)[u] = packb(q0, q1);
    reinterpret_cast<uint32_t*>(g_Kh)[u] = packb(k0, k1);
    reinterpret_cast<uint32_t*>(g_Ql)[u] = packb(
        __float2bfloat16_rn(qv.x - __bfloat162float(q0)),
        __float2bfloat16_rn(qv.y - __bfloat162float(q1)));
    reinterpret_cast<uint32_t*>(g_Kl)[u] = packb(
        __float2bfloat16_rn(kv.x - __bfloat162float(k0)),
        __float2bfloat16_rn(kv.y - __bfloat162float(k1)));
}

// ---------------- kernel 2b: v [b,s,e] -> head-major bf16 hi/lo -------------
__global__ __launch_bounds__(256) void convv_kernel(const float* __restrict__ v)
{
    int u = blockIdx.x * 256 + threadIdx.x;   // pair id (head-major)
    int i = u * 2;
    int d  = i & (HD - 1);
    int s  = (i >> 6) & (S - 1);
    int bh = i >> 17;
    int h = bh & (H - 1), b = bh >> 4;
    float2 vv = *reinterpret_cast<const float2*>(
        v + (size_t)(b * S + s) * E + h * HD + d);
    __nv_bfloat16 v0 = __float2bfloat16_rn(vv.x), v1 = __float2bfloat16_rn(vv.y);
    reinterpret_cast<uint32_t*>(g_Vh)[u] = packb(v0, v1);
    reinterpret_cast<uint32_t*>(g_Vl)[u] = packb(
        __float2bfloat16_rn(vv.x - __bfloat162float(v0)),
        __float2bfloat16_rn(vv.y - __bfloat162float(v1)));
}

// ---------------- kernel 3: flash attention (bf16x3 mma, explicit LDS) ------
// 256 threads = 8 warps; warp w owns rows [16w,16w+16) of a 128-row q tile.
__global__ __launch_bounds__(256) void attn_kernel()
{
    extern __shared__ __nv_bfloat16 smb[];
    __nv_bfloat16* sQh  = smb;              // [128][LDT]
    __nv_bfloat16* sQl  = smb + 9216;
    __nv_bfloat16* sKh  = smb + 18432;      // [64][LDT]  (row kv, col d)
    __nv_bfloat16* sKl  = smb + 23040;
    __nv_bfloat16* sVth = smb + 27648;      // [64][LDT]  V transposed (row d, col kv)
    __nv_bfloat16* sVtl = smb + 32256;

    int bh = blockIdx.y, qt = blockIdx.x;
    int tid = threadIdx.x, w = tid >> 5, t = tid & 31;
    int gid = t >> 2, tig = t & 3;
    int w16 = w * 16;

    size_t base = (size_t)bh * S * HD;
    const __nv_bfloat16* Qhb = g_Qh + base + (size_t)qt * BMA * HD;
    const __nv_bfloat16* Qlb = g_Ql + base + (size_t)qt * BMA * HD;
    const __nv_bfloat16* Khb = g_Kh + base;
    const __nv_bfloat16* Klb = g_Kl + base;
    const __nv_bfloat16* Vhb = g_Vh + base;
    const __nv_bfloat16* Vlb = g_Vl + base;

    #pragma unroll
    for (int i = 0; i < 4; i++) {
        int lin = i * 256 + tid;
        int r = lin >> 3, c = lin & 7;
        *reinterpret_cast<uint4*>(sQh + r * LDT + c * 8) =
            *reinterpret_cast<const uint4*>(Qhb + r * HD + c * 8);
        *reinterpret_cast<uint4*>(sQl + r * LDT + c * 8) =
            *reinterpret_cast<const uint4*>(Qlb + r * HD + c * 8);
    }

    float accO[8][4];
    #pragma unroll
    for (int j = 0; j < 8; j++)
        #pragma unroll
        for (int c = 0; c < 4; c++) accO[j][c] = 0.f;
    float m0 = -1e30f, m1 = -1e30f, l0 = 0.f, l1 = 0.f;

    for (int kt = 0; kt < S / BNA; kt++) {
        __syncthreads();
        #pragma unroll
        for (int i = 0; i < 2; i++) {
            int lin = i * 256 + tid;
            int r = lin >> 3, c = lin & 7;
            size_t g = (size_t)(kt * BNA + r) * HD + c * 8;
            *reinterpret_cast<uint4*>(sKh + r * LDT + c * 8) =
                *reinterpret_cast<const uint4*>(Khb + g);
            *reinterpret_cast<uint4*>(sKl + r * LDT + c * 8) =
                *reinterpret_cast<const uint4*>(Klb + g);
            uint4 vh = *reinterpret_cast<const uint4*>(Vhb + g);
            uint4 vl = *reinterpret_cast<const uint4*>(Vlb + g);
            const __nv_bfloat16* ph = reinterpret_cast<const __nv_bfloat16*>(&vh);
            const __nv_bfloat16* pl = reinterpret_cast<const __nv_bfloat16*>(&vl);
            #pragma unroll
            for (int jj = 0; jj < 8; jj++) {
                sVth[(c * 8 + jj) * LDT + r] = ph[jj];
                sVtl[(c * 8 + jj) * LDT + r] = pl[jj];
            }
        }
        __syncthreads();

        // ---- S = Q K^T (bf16x3) ----
        float accS[8][4];
        #pragma unroll
        for (int j = 0; j < 8; j++)
            #pragma unroll
            for (int c = 0; c < 4; c++) accS[j][c] = 0.f;

        #pragma unroll
        for (int kk = 0; kk < 4; kk++) {
            int kb = kk * 16 + 2 * tig;
            const __nv_bfloat16* q0h = sQh + (w16 + gid) * LDT + kb;
            const __nv_bfloat16* q0l = sQl + (w16 + gid) * LDT + kb;
            uint32_t ah[4], al[4];
            ah[0] = lds32(q0h);               al[0] = lds32(q0l);
            ah[1] = lds32(q0h + 8 * LDT);     al[1] = lds32(q0l + 8 * LDT);
            ah[2] = lds32(q0h + 8);           al[2] = lds32(q0l + 8);
            ah[3] = lds32(q0h + 8 * LDT + 8); al[3] = lds32(q0l + 8 * LDT + 8);
            #pragma unroll
            for (int j = 0; j < 8; j++) {
                const __nv_bfloat16* kr_h = sKh + (j * 8 + gid) * LDT + kb;
                const __nv_bfloat16* kr_l = sKl + (j * 8 + gid) * LDT + kb;
                uint32_t bhf[2] = { lds32(kr_h), lds32(kr_h + 8) };
                uint32_t blf[2] = { lds32(kr_l), lds32(kr_l + 8) };
                mma16816(accS[j], ah, bhf);
                mma16816(accS[j], ah, blf);
                mma16816(accS[j], al, bhf);
            }
        }

        // ---- online softmax (log2 domain) ----
        float mx0 = -1e30f, mx1 = -1e30f;
        #pragma unroll
        for (int j = 0; j < 8; j++) {
            mx0 = fmaxf(mx0, fmaxf(accS[j][0], accS[j][1]));
            mx1 = fmaxf(mx1, fmaxf(accS[j][2], accS[j][3]));
        }
        #pragma unroll
        for (int off = 1; off <= 2; off <<= 1) {
            mx0 = fmaxf(mx0, __shfl_xor_sync(0xffffffff, mx0, off));
            mx1 = fmaxf(mx1, __shfl_xor_sync(0xffffffff, mx1, off));
        }
        float mn0 = fmaxf(m0, mx0), mn1 = fmaxf(m1, mx1);
        float sc0 = exp2f(m0 - mn0), sc1 = exp2f(m1 - mn1);
        m0 = mn0; m1 = mn1;
        float rs0 = 0.f, rs1 = 0.f;
        #pragma unroll
        for (int j = 0; j < 8; j++) {
            accS[j][0] = exp2f(accS[j][0] - mn0);
            accS[j][1] = exp2f(accS[j][1] - mn0);
            accS[j][2] = exp2f(accS[j][2] - mn1);
            accS[j][3] = exp2f(accS[j][3] - mn1);
            rs0 += accS[j][0] + accS[j][1];
            rs1 += accS[j][2] + accS[j][3];
        }
        #pragma unroll
        for (int off = 1; off <= 2; off <<= 1) {
            rs0 += __shfl_xor_sync(0xffffffff, rs0, off);
            rs1 += __shfl_xor_sync(0xffffffff, rs1, off);
        }
        l0 = l0 * sc0 + rs0;
        l1 = l1 * sc1 + rs1;
        #pragma unroll
        for (int j = 0; j < 8; j++) {
            accO[j][0] *= sc0; accO[j][1] *= sc0;
            accO[j][2] *= sc1; accO[j][3] *= sc1;
        }

        // ---- O += P V (bf16x2 P hi/lo as A fragments) ----
        #pragma unroll
        for (int kk = 0; kk < 4; kk++) {
            const float* p0 = accS[2 * kk];
            const float* p1 = accS[2 * kk + 1];
            __nv_bfloat16 h00 = __float2bfloat16_rn(p0[0]);
            __nv_bfloat16 h01 = __float2bfloat16_rn(p0[1]);
            __nv_bfloat16 h02 = __float2bfloat16_rn(p0[2]);
            __nv_bfloat16 h03 = __float2bfloat16_rn(p0[3]);
            __nv_bfloat16 h10 = __float2bfloat16_rn(p1[0]);
            __nv_bfloat16 h11 = __float2bfloat16_rn(p1[1]);
            __nv_bfloat16 h12 = __float2bfloat16_rn(p1[2]);
            __nv_bfloat16 h13 = __float2bfloat16_rn(p1[3]);
            uint32_t pah[4] = { packb(h00, h01), packb(h02, h03),
                                packb(h10, h11), packb(h12, h13) };
            uint32_t pal[4] = {
                packb(__float2bfloat16_rn(p0[0] - __bfloat162float(h00)),
                      __float2bfloat16_rn(p0[1] - __bfloat162float(h01))),
                packb(__float2bfloat16_rn(p0[2] - __bfloat162float(h02)),
                      __float2bfloat16_rn(p0[3] - __bfloat162float(h03))),
                packb(__float2bfloat16_rn(p1[0] - __bfloat162float(h10)),
                      __float2bfloat16_rn(p1[1] - __bfloat162float(h11))),
                packb(__float2bfloat16_rn(p1[2] - __bfloat162float(h12)),
                      __float2bfloat16_rn(p1[3] - __bfloat162float(h13))) };
            int kvb = kk * 16 + 2 * tig;
            #pragma unroll
            for (int j = 0; j < 8; j++) {
                const __nv_bfloat16* vr_h = sVth + (j * 8 + gid) * LDT + kvb;
                const __nv_bfloat16* vr_l = sVtl + (j * 8 + gid) * LDT + kvb;
                uint32_t vbh[2] = { lds32(vr_h), lds32(vr_h + 8) };
                uint32_t vbl[2] = { lds32(vr_l), lds32(vr_l + 8) };
                mma16816(accO[j], pah, vbh);
                mma16816(accO[j], pah, vbl);
                mma16816(accO[j], pal, vbh);
            }
        }
    }

    // ---- epilogue: normalize, write fp32 ctx ----
    int b = bh >> 4, h = bh & 15;
    float i0 = 1.0f / l0, i1 = 1.0f / l1;
    int row0 = b * S + qt * BMA + w16 + gid;
    int row1 = row0 + 8;
    #pragma unroll
    for (int j = 0; j < 8; j++) {
        int col = h * HD + j * 8 + 2 * tig;
        float2 o0 = make_float2(accO[j][0] * i0, accO[j][1] * i0);
        float2 o1 = make_float2(accO[j][2] * i1, accO[j][3] * i1);
        *reinterpret_cast<float2*>(g_ctx + (size_t)row0 * E + col) = o0;
        *reinterpret_cast<float2*>(g_ctx + (size_t)row1 * E + col) = o1;
    }
}

// ---------------- kernel 4: projection (EXACT copy of R1-passing) -----------
__global__ __launch_bounds__(256) void proj_kernel(
    const float* __restrict__ W, const float* __restrict__ bias,
    float* __restrict__ out)
{
    __shared__ float sA[64 * 16];    // (m, k)
    __shared__ float sBt[16 * 68];   // (k, j)

    int tid = threadIdx.x;
    int tx = tid & 15, ty = tid >> 4;
    int jb = blockIdx.x * 64, mb = blockIdx.y * 64;
    int r = tid >> 2, c4 = (tid & 3) << 2;

    float acc[4][4];
    #pragma unroll
    for (int i = 0; i < 4; i++)
        #pragma unroll
        for (int j = 0; j < 4; j++) acc[i][j] = 0.f;

    for (int kt = 0; kt < E; kt += 16) {
        __syncthreads();
        float4 a = *reinterpret_cast<const float4*>(g_ctx + (mb + r) * E + kt + c4);
        *reinterpret_cast<float4*>(sA + r * 16 + c4) = a;
        float4 w = *reinterpret_cast<const float4*>(W + (jb + r) * E + kt + c4);
        sBt[(c4 + 0) * 68 + r] = w.x;
        sBt[(c4 + 1) * 68 + r] = w.y;
        sBt[(c4 + 2) * 68 + r] = w.z;
        sBt[(c4 + 3) * 68 + r] = w.w;
        __syncthreads();

        #pragma unroll
        for (int kk = 0; kk < 16; kk += 4) {
            float4 af[4], bf[4];
            #pragma unroll
            for (int i = 0; i < 4; i++)
                af[i] = *reinterpret_cast<const float4*>(sA + (ty * 4 + i) * 16 + kk);
            #pragma unroll
            for (int d = 0; d < 4; d++)
                bf[d] = *reinterpret_cast<const float4*>(sBt + (kk + d) * 68 + tx * 4);
            #pragma unroll
            for (int d = 0; d < 4; d++) {
                float bx = C4(bf[d], 0), by = C4(bf[d], 1);
                float bz = C4(bf[d], 2), bw = C4(bf[d], 3);
                #pragma unroll
                for (int i = 0; i < 4; i++) {
                    float ad = C4(af[i], d);
                    acc[i][0] = fmaf(ad, bx, acc[i][0]);
                    acc[i][1] = fmaf(ad, by, acc[i][1]);
                    acc[i][2] = fmaf(ad, bz, acc[i][2]);
                    acc[i][3] = fmaf(ad, bw, acc[i][3]);
                }
            }
        }
    }

    float4 bb = *reinterpret_cast<const float4*>(bias + jb + tx * 4);
    #pragma unroll
    for (int i = 0; i < 4; i++) {
        float4 rv = make_float4(acc[i][0] + bb.x, acc[i][1] + bb.y,
                                acc[i][2] + bb.z, acc[i][3] + bb.w);
        *reinterpret_cast<float4*>(out + (mb + ty * 4 + i) * E + jb + tx * 4) = rv;
    }
}

// ---------------------------------------------------------------------------
extern "C" void kernel_launch(void* const* d_in, const int* in_sizes, int n_in,
                              void* d_out, int out_size)
{
    const float* q    = (const float*)d_in[0];
    const float* k    = (const float*)d_in[1];
    const float* v    = (const float*)d_in[2];
    const float* qw   = (const float*)d_in[3];
    const float* kw   = (const float*)d_in[4];
    const float* W    = (const float*)d_in[5];
    const float* bias = (const float*)d_in[6];
    float* out = (float*)d_out;

    cudaFuncSetAttribute(attn_kernel,
                         cudaFuncAttributeMaxDynamicSharedMemorySize, SMEM_ATTN);

    prep_kernel<<<(B * S * H) / 8, 256>>>(q, k, qw, kw);
    convqk_kernel<<<(B * H * S * HD) / 512, 256>>>();
    convv_kernel<<<(B * H * S * HD) / 512, 256>>>(v);
    attn_kernel<<<dim3(S / BMA, B * H), 256, SMEM_ATTN>>>();
    proj_kernel<<<dim3(E / 64, (B * S) / 64), 256>>>(W, bias, out);
}